// round 7
// baseline (speedup 1.0000x reference)
#include <cuda_runtime.h>
#include <stdint.h>
#include <math.h>

#define NVARS    4000
#define NLITS    8000
#define NCLAUSES 16800
#define NEDGES   50400
#define FMAPS    256

// ---------------- device scratch (allocation-free) ----------------
__device__ float g_lh  [NLITS   * FMAPS];
__device__ float g_lc  [NLITS   * FMAPS];
__device__ float g_ch  [NCLAUSES* FMAPS];
__device__ float g_cc  [NCLAUSES* FMAPS];
__device__ float g_h1  [NCLAUSES* FMAPS];
__device__ float g_h2  [NCLAUSES* FMAPS];
__device__ float g_cmsg[NCLAUSES* FMAPS];
__device__ float g_lmsg[NLITS   * FMAPS];
__device__ float g_flip[NLITS   * FMAPS];
__device__ float g_z   [NCLAUSES* 4 * FMAPS];
__device__ float g_vbuf[NVARS * 2 * FMAPS];
__device__ float g_vh1 [NVARS * 2 * FMAPS];
__device__ float g_vh2 [NVARS * 2 * FMAPS];
__device__ float g_logits[NVARS];
__device__ float g_loss[1];
__device__ int   g_litidx[NEDGES];
__device__ int   g_varidx[NEDGES];
__device__ float g_sign [NEDGES];

// ================= 3xTF32 split-precision tensor-core GEMM =================
// C[M,N] = A[M,K] @ B[K,N]  (row-major A and B), fp32-accurate via hi/lo split.
// flags: 1=add bias, 2=relu, 4=accumulate into existing C
#define BM 128
#define BN 128
#define BK 32
#define ASTR (BK + 4)
#define BSTR (BN + 4)
#define ASZ (BM * ASTR)
#define BSZ (BK * BSTR)
#define STAGE (ASZ + BSZ)

__device__ __forceinline__ void cp16(uint32_t saddr, const void* g, int src_bytes)
{
    asm volatile("cp.async.ca.shared.global [%0], [%1], 16, %2;\n"
                 :: "r"(saddr), "l"(g), "r"(src_bytes));
}

__device__ __forceinline__ uint32_t f2tf32(float x)
{
    uint32_t r;
    asm("cvt.rna.tf32.f32 %0, %1;\n" : "=r"(r) : "f"(x));
    return r;
}

__device__ __forceinline__ void mma_tf32(float* c, uint32_t a0, uint32_t a1,
                                         uint32_t a2, uint32_t a3,
                                         uint32_t b0, uint32_t b1)
{
    asm volatile(
        "mma.sync.aligned.m16n8k8.row.col.f32.tf32.tf32.f32 "
        "{%0,%1,%2,%3}, {%4,%5,%6,%7}, {%8,%9}, {%0,%1,%2,%3};\n"
        : "+f"(c[0]), "+f"(c[1]), "+f"(c[2]), "+f"(c[3])
        : "r"(a0), "r"(a1), "r"(a2), "r"(a3), "r"(b0), "r"(b1));
}

__global__ __launch_bounds__(256)
void tgemm(const float* __restrict__ A, const float* __restrict__ B,
           const float* __restrict__ bias, float* __restrict__ C,
           int M, int N, int K, int flags)
{
    extern __shared__ float sm[];
    const int tid  = threadIdx.x;
    const int warp = tid >> 5, lane = tid & 31;
    const int gid  = lane >> 2, ti = lane & 3;
    const int wm = warp >> 2, wn = warp & 3;         // 2 x 4 warp grid
    const int warpRow = wm * 64, warpCol = wn * 32;
    const int bm = blockIdx.y * BM, bn = blockIdx.x * BN;
    const int nit = K / BK;

    float c[4][4][4];
#pragma unroll
    for (int mi = 0; mi < 4; mi++)
#pragma unroll
        for (int ni = 0; ni < 4; ni++)
#pragma unroll
            for (int r = 0; r < 4; r++) c[mi][ni][r] = 0.f;

    // ---- prefetch stage 0 ----
    {
        float* As = sm;            float* Bs = sm + ASZ;
#pragma unroll
        for (int i = 0; i < 4; i++) {
            int idx = tid + i * 256;
            int ar = idx >> 3, ac = (idx & 7) << 2;
            int ok = (bm + ar) < M;
            const float* src = A + (size_t)(ok ? (bm + ar) : 0) * K + ac;
            cp16((uint32_t)__cvta_generic_to_shared(As + ar * ASTR + ac), src, ok ? 16 : 0);
            int br = idx >> 5, bc = (idx & 31) << 2;
            cp16((uint32_t)__cvta_generic_to_shared(Bs + br * BSTR + bc),
                 B + (size_t)br * N + bn + bc, 16);
        }
        asm volatile("cp.async.commit_group;\n");
    }

    for (int it = 0; it < nit; it++) {
        if (it + 1 < nit) {
            const int k0 = (it + 1) * BK;
            float* As = sm + ((it + 1) & 1) * STAGE;
            float* Bs = As + ASZ;
#pragma unroll
            for (int i = 0; i < 4; i++) {
                int idx = tid + i * 256;
                int ar = idx >> 3, ac = (idx & 7) << 2;
                int ok = (bm + ar) < M;
                const float* src = A + (size_t)(ok ? (bm + ar) : 0) * K + k0 + ac;
                cp16((uint32_t)__cvta_generic_to_shared(As + ar * ASTR + ac), src, ok ? 16 : 0);
                int br = idx >> 5, bc = (idx & 31) << 2;
                cp16((uint32_t)__cvta_generic_to_shared(Bs + br * BSTR + bc),
                     B + (size_t)(k0 + br) * N + bn + bc, 16);
            }
            asm volatile("cp.async.commit_group;\n");
            asm volatile("cp.async.wait_group 1;\n");
        } else {
            asm volatile("cp.async.wait_group 0;\n");
        }
        __syncthreads();

        const float* As = sm + (it & 1) * STAGE;
        const float* Bs = As + ASZ;

#pragma unroll
        for (int kk = 0; kk < 4; kk++) {
            const int ks = kk * 8;
            uint32_t ah[4][4], al[4][4], bh[4][2], bl[4][2];
#pragma unroll
            for (int mi = 0; mi < 4; mi++) {
                int r0 = warpRow + mi * 16 + gid;
                float v0 = As[(r0)     * ASTR + ks + ti];
                float v1 = As[(r0 + 8) * ASTR + ks + ti];
                float v2 = As[(r0)     * ASTR + ks + ti + 4];
                float v3 = As[(r0 + 8) * ASTR + ks + ti + 4];
                ah[mi][0] = f2tf32(v0); al[mi][0] = f2tf32(v0 - __uint_as_float(ah[mi][0]));
                ah[mi][1] = f2tf32(v1); al[mi][1] = f2tf32(v1 - __uint_as_float(ah[mi][1]));
                ah[mi][2] = f2tf32(v2); al[mi][2] = f2tf32(v2 - __uint_as_float(ah[mi][2]));
                ah[mi][3] = f2tf32(v3); al[mi][3] = f2tf32(v3 - __uint_as_float(ah[mi][3]));
            }
#pragma unroll
            for (int ni = 0; ni < 4; ni++) {
                int cc = warpCol + ni * 8 + gid;
                float v0 = Bs[(ks + ti)     * BSTR + cc];
                float v1 = Bs[(ks + ti + 4) * BSTR + cc];
                bh[ni][0] = f2tf32(v0); bl[ni][0] = f2tf32(v0 - __uint_as_float(bh[ni][0]));
                bh[ni][1] = f2tf32(v1); bl[ni][1] = f2tf32(v1 - __uint_as_float(bh[ni][1]));
            }
#pragma unroll
            for (int mi = 0; mi < 4; mi++)
#pragma unroll
                for (int ni = 0; ni < 4; ni++) {
                    float* acc = c[mi][ni];
                    // corrections first, big term last
                    mma_tf32(acc, ah[mi][0], ah[mi][1], ah[mi][2], ah[mi][3],
                                  bl[ni][0], bl[ni][1]);
                    mma_tf32(acc, al[mi][0], al[mi][1], al[mi][2], al[mi][3],
                                  bh[ni][0], bh[ni][1]);
                    mma_tf32(acc, ah[mi][0], ah[mi][1], ah[mi][2], ah[mi][3],
                                  bh[ni][0], bh[ni][1]);
                }
        }
        __syncthreads();
    }

    // ---- epilogue ----
#pragma unroll
    for (int mi = 0; mi < 4; mi++) {
        int r0 = bm + warpRow + mi * 16 + gid;
        int r1 = r0 + 8;
#pragma unroll
        for (int ni = 0; ni < 4; ni++) {
            int c0 = bn + warpCol + ni * 8 + ti * 2;
#pragma unroll
            for (int half = 0; half < 2; half++) {
                int row = half ? r1 : r0;
                if (row >= M) continue;
                float v0 = c[mi][ni][half * 2 + 0];
                float v1 = c[mi][ni][half * 2 + 1];
                if (flags & 1) { v0 += bias[c0]; v1 += bias[c0 + 1]; }
                size_t o = (size_t)row * N + c0;
                if (flags & 4) { v0 += C[o]; v1 += C[o + 1]; }
                if (flags & 2) { v0 = fmaxf(v0, 0.f); v1 = fmaxf(v1, 0.f); }
                C[o] = v0; C[o + 1] = v1;
            }
        }
    }
}

// ---------------- elementwise / graph kernels ----------------
__global__ void k_build_edges(const int* __restrict__ lits,
                              int* litidx, int* varidx, float* sign)
{
    int e = blockIdx.x * blockDim.x + threadIdx.x;
    if (e >= NEDGES) return;
    int l = lits[e];
    int v = (l > 0 ? l : -l) - 1;
    varidx[e] = v;
    litidx[e] = (l > 0) ? v : (NVARS + v);
    sign[e]   = (l > 0) ? 1.f : -1.f;
}

__global__ void k_bcast_init(float* h, float* c, const float* __restrict__ init, int rows)
{
    int i = blockIdx.x * blockDim.x + threadIdx.x;
    if (i >= rows * FMAPS) return;
    h[i] = init[i & (FMAPS - 1)] * 0.0625f;   // 1/sqrt(256)
    c[i] = 0.f;
}

__global__ void k_zero(float* p, int n)
{
    int i = blockIdx.x * blockDim.x + threadIdx.x;
    if (i < n) p[i] = 0.f;
}

__global__ void k_gather_clause(const float* __restrict__ pre,
                                const int* __restrict__ litidx,
                                float* __restrict__ msgs)
{
    int idx = blockIdx.x * blockDim.x + threadIdx.x;
    if (idx >= NCLAUSES * FMAPS) return;
    int c = idx >> 8, f = idx & 255;
    int e = c * 3;
    float s = pre[(size_t)litidx[e]     * FMAPS + f]
            + pre[(size_t)litidx[e + 1] * FMAPS + f]
            + pre[(size_t)litidx[e + 2] * FMAPS + f];
    msgs[idx] = s;
}

__global__ void k_scatter_lit(const float* __restrict__ pre,
                              const int* __restrict__ litidx,
                              float* __restrict__ msgs)
{
    int idx = blockIdx.x * blockDim.x + threadIdx.x;
    if (idx >= NEDGES * FMAPS) return;
    int e = idx >> 8, f = idx & 255;
    int c = e / 3;
    atomicAdd(&msgs[(size_t)litidx[e] * FMAPS + f], pre[(size_t)c * FMAPS + f]);
}

__device__ __forceinline__ float sigf(float x) { return 1.f / (1.f + expf(-x)); }

__global__ void k_lstm_update(const float* __restrict__ z,
                              float* __restrict__ h, float* __restrict__ c, int rows)
{
    int idx = blockIdx.x * blockDim.x + threadIdx.x;
    if (idx >= rows * FMAPS) return;
    int r = idx >> 8, f = idx & 255;
    const float* zr = z + (size_t)r * (4 * FMAPS);
    float gi = zr[f], gf = zr[FMAPS + f], gg = zr[2 * FMAPS + f], go = zr[3 * FMAPS + f];
    float cn = sigf(gf) * c[idx] + sigf(gi) * tanhf(gg);
    c[idx] = cn;
    h[idx] = sigf(go) * tanhf(cn);
}

__global__ void k_flip(const float* __restrict__ lh, float* __restrict__ flip)
{
    int idx = blockIdx.x * blockDim.x + threadIdx.x;
    if (idx >= NLITS * FMAPS) return;
    int r = idx >> 8, f = idx & 255;
    int src = (r < NVARS) ? (r + NVARS) : (r - NVARS);
    flip[idx] = lh[(size_t)src * FMAPS + f];
}

__global__ void k_vbuf(const float* __restrict__ lh, float* __restrict__ vbuf)
{
    int idx = blockIdx.x * blockDim.x + threadIdx.x;
    if (idx >= NVARS * 2 * FMAPS) return;
    int v = idx >> 9, f = idx & 511;
    float val = (f < FMAPS) ? lh[(size_t)v * FMAPS + f]
                            : lh[(size_t)(NVARS + v) * FMAPS + (f - FMAPS)];
    vbuf[idx] = val;
}

__global__ void k_vote_out(const float* __restrict__ H, const float* __restrict__ W2,
                           const float* __restrict__ b2, float* __restrict__ logits)
{
    int warp = (blockIdx.x * blockDim.x + threadIdx.x) >> 5;
    int lane = threadIdx.x & 31;
    if (warp >= NVARS) return;
    const float* h = H + (size_t)warp * (2 * FMAPS);
    float s = 0.f;
#pragma unroll
    for (int k = lane; k < 2 * FMAPS; k += 32) s += h[k] * W2[k];
#pragma unroll
    for (int o = 16; o; o >>= 1) s += __shfl_down_sync(0xffffffffu, s, o);
    if (lane == 0) logits[warp] = s + b2[0];
}

__device__ __forceinline__ float softplusf(float x)
{
    return fmaxf(x, 0.f) + log1pf(expf(-fabsf(x)));
}

__global__ void k_loss(const float* __restrict__ logits,
                       const int* __restrict__ varidx,
                       const float* __restrict__ sign,
                       float* __restrict__ loss)
{
    __shared__ float red[256];
    int c = blockIdx.x * blockDim.x + threadIdx.x;
    float t = 0.f;
    if (c < NCLAUSES) {
        float s = 0.f;
#pragma unroll
        for (int k = 0; k < 3; k++) {
            int e = c * 3 + k;
            s += softplusf(logits[varidx[e]] * sign[e]);
        }
        float cv = expf(-s);
        float v = -logf(1.f - cv + 1e-8f);
        t = v * v;
    }
    red[threadIdx.x] = t;
    __syncthreads();
    for (int o = 128; o; o >>= 1) {
        if (threadIdx.x < o) red[threadIdx.x] += red[threadIdx.x + o];
        __syncthreads();
    }
    if (threadIdx.x == 0) atomicAdd(loss, red[0]);
}

__global__ void k_writeout(const float* __restrict__ logits,
                           const float* __restrict__ loss,
                           float* __restrict__ out, int out_size)
{
    int i = blockIdx.x * blockDim.x + threadIdx.x;
    if (i < NVARS && i < out_size) out[i] = logits[i];
    if (i == NVARS && out_size > NVARS) out[NVARS] = loss[0] / 32.0f;
}

// ---------------- host orchestration ----------------
static const int SMEM_BYTES = STAGE * 2 * sizeof(float);   // ~70.7 KB

static inline void gemm(const float* A, const float* B, const float* bias, float* C,
                        int M, int N, int K, int flags)
{
    dim3 g(N / BN, (M + BM - 1) / BM);
    tgemm<<<g, 256, SMEM_BYTES>>>(A, B, bias, C, M, N, K, flags);
}

static inline int gdiv(int a, int b) { return (a + b - 1) / b; }

extern "C" void kernel_launch(void* const* d_in, const int* in_sizes, int n_in,
                              void* d_out, int out_size)
{
    static int smem_set = 0;
    if (!smem_set) {
        cudaFuncSetAttribute(tgemm, cudaFuncAttributeMaxDynamicSharedMemorySize, SMEM_BYTES);
        smem_set = 1;
    }

    int p = 1;
    if (n_in > 1 && in_sizes[1] == 1) p = 2;
    const int*   clause_lits = (const int*)d_in[0];
    const float* L_init = (const float*)d_in[p + 0];
    const float* C_init = (const float*)d_in[p + 1];
    const float* LC_W0  = (const float*)d_in[p + 2];
    const float* LC_b0  = (const float*)d_in[p + 3];
    const float* LC_W1  = (const float*)d_in[p + 4];
    const float* LC_b1  = (const float*)d_in[p + 5];
    const float* LC_W2  = (const float*)d_in[p + 6];
    const float* LC_b2  = (const float*)d_in[p + 7];
    const float* CL_W0  = (const float*)d_in[p + 8];
    const float* CL_b0  = (const float*)d_in[p + 9];
    const float* CL_W1  = (const float*)d_in[p + 10];
    const float* CL_b1  = (const float*)d_in[p + 11];
    const float* CL_W2  = (const float*)d_in[p + 12];
    const float* CL_b2  = (const float*)d_in[p + 13];
    const float* C_Wx   = (const float*)d_in[p + 14];
    const float* C_Wh   = (const float*)d_in[p + 15];
    const float* C_b    = (const float*)d_in[p + 16];
    const float* L_Wx   = (const float*)d_in[p + 17];
    const float* L_Wh   = (const float*)d_in[p + 18];
    const float* L_b    = (const float*)d_in[p + 19];
    const float* V_W0   = (const float*)d_in[p + 20];
    const float* V_b0   = (const float*)d_in[p + 21];
    const float* V_W1   = (const float*)d_in[p + 22];
    const float* V_b1   = (const float*)d_in[p + 23];
    const float* V_W2   = (const float*)d_in[p + 24];
    const float* V_b2   = (const float*)d_in[p + 25];
    float* out = (float*)d_out;

    float *lh, *lc, *ch, *cc, *h1, *h2, *cmsg, *lmsg, *flip, *z, *vbuf, *vh1, *vh2, *logits, *loss, *sign;
    int *litidx, *varidx;
    cudaGetSymbolAddress((void**)&lh,   g_lh);
    cudaGetSymbolAddress((void**)&lc,   g_lc);
    cudaGetSymbolAddress((void**)&ch,   g_ch);
    cudaGetSymbolAddress((void**)&cc,   g_cc);
    cudaGetSymbolAddress((void**)&h1,   g_h1);
    cudaGetSymbolAddress((void**)&h2,   g_h2);
    cudaGetSymbolAddress((void**)&cmsg, g_cmsg);
    cudaGetSymbolAddress((void**)&lmsg, g_lmsg);
    cudaGetSymbolAddress((void**)&flip, g_flip);
    cudaGetSymbolAddress((void**)&z,    g_z);
    cudaGetSymbolAddress((void**)&vbuf, g_vbuf);
    cudaGetSymbolAddress((void**)&vh1,  g_vh1);
    cudaGetSymbolAddress((void**)&vh2,  g_vh2);
    cudaGetSymbolAddress((void**)&logits, g_logits);
    cudaGetSymbolAddress((void**)&loss, g_loss);
    cudaGetSymbolAddress((void**)&sign, g_sign);
    cudaGetSymbolAddress((void**)&litidx, g_litidx);
    cudaGetSymbolAddress((void**)&varidx, g_varidx);

    const float* L_Wx_top = L_Wx;                   // rows [0,256)   -> cl_msgs part
    const float* L_Wx_bot = L_Wx + 256 * 1024;      // rows [256,512) -> flipped part

    // ---- setup ----
    k_build_edges<<<gdiv(NEDGES, 256), 256>>>(clause_lits, litidx, varidx, sign);
    k_bcast_init<<<gdiv(NLITS * FMAPS, 256), 256>>>(lh, lc, L_init, NLITS);
    k_bcast_init<<<gdiv(NCLAUSES * FMAPS, 256), 256>>>(ch, cc, C_init, NCLAUSES);
    k_zero<<<1, 32>>>(loss, 1);

    // ---- 32 message-passing rounds ----
    for (int r = 0; r < 32; r++) {
        gemm(lh, LC_W0, LC_b0, h1, NLITS, FMAPS, FMAPS, 1 | 2);
        gemm(h1, LC_W1, LC_b1, h2, NLITS, FMAPS, FMAPS, 1 | 2);
        gemm(h2, LC_W2, LC_b2, h1, NLITS, FMAPS, FMAPS, 1);
        k_gather_clause<<<gdiv(NCLAUSES * FMAPS, 256), 256>>>(h1, litidx, cmsg);
        gemm(cmsg, C_Wx, C_b, z, NCLAUSES, 4 * FMAPS, FMAPS, 1);
        gemm(ch,   C_Wh, 0,   z, NCLAUSES, 4 * FMAPS, FMAPS, 4);
        k_lstm_update<<<gdiv(NCLAUSES * FMAPS, 256), 256>>>(z, ch, cc, NCLAUSES);
        gemm(ch, CL_W0, CL_b0, h1, NCLAUSES, FMAPS, FMAPS, 1 | 2);
        gemm(h1, CL_W1, CL_b1, h2, NCLAUSES, FMAPS, FMAPS, 1 | 2);
        gemm(h2, CL_W2, CL_b2, h1, NCLAUSES, FMAPS, FMAPS, 1);
        k_zero<<<gdiv(NLITS * FMAPS, 256), 256>>>(lmsg, NLITS * FMAPS);
        k_scatter_lit<<<gdiv(NEDGES * FMAPS, 256), 256>>>(h1, litidx, lmsg);
        k_flip<<<gdiv(NLITS * FMAPS, 256), 256>>>(lh, flip);
        gemm(lmsg, L_Wx_top, L_b, z, NLITS, 4 * FMAPS, FMAPS, 1);
        gemm(flip, L_Wx_bot, 0,   z, NLITS, 4 * FMAPS, FMAPS, 4);
        gemm(lh,   L_Wh,     0,   z, NLITS, 4 * FMAPS, FMAPS, 4);
        k_lstm_update<<<gdiv(NLITS * FMAPS, 256), 256>>>(z, lh, lc, NLITS);
        k_vbuf<<<gdiv(NVARS * 2 * FMAPS, 256), 256>>>(lh, vbuf);
        gemm(vbuf, V_W0, V_b0, vh1, NVARS, 2 * FMAPS, 2 * FMAPS, 1 | 2);
        gemm(vh1,  V_W1, V_b1, vh2, NVARS, 2 * FMAPS, 2 * FMAPS, 1 | 2);
        k_vote_out<<<gdiv(NVARS * 32, 256), 256>>>(vh2, V_W2, V_b2, logits);
        k_loss<<<gdiv(NCLAUSES, 256), 256>>>(logits, varidx, sign, loss);
    }

    k_writeout<<<gdiv(NVARS + 1, 256), 256>>>(logits, loss, out, out_size);
}

// round 15
// speedup vs baseline: 1.4189x; 1.4189x over previous
#include <cuda_runtime.h>
#include <cuda_fp16.h>
#include <stdint.h>
#include <math.h>

#define NVARS    4000
#define NLITS    8000
#define NCLAUSES 16800
#define NEDGES   50400
#define FMAPS    256

// section scale: sec1 = hi/SSC paired with lo*SSC ; sec2 = lo*SSC paired with hi/SSC
#define SSC     128.0f
#define SSC_INV 0.0078125f

// ---------------- device scratch (allocation-free) ----------------
__device__ float g_lh  [NLITS   * FMAPS];
__device__ float g_lc  [NLITS   * FMAPS];
__device__ float g_ch  [NCLAUSES* FMAPS];
__device__ float g_cc  [NCLAUSES* FMAPS];
__device__ float g_h1  [NCLAUSES* FMAPS];
__device__ float g_h2  [NCLAUSES* FMAPS];
__device__ float g_cmsg[NCLAUSES* FMAPS];
__device__ float g_lmsg[NLITS   * FMAPS];
__device__ float g_flip[NLITS   * FMAPS];
__device__ float g_z   [NCLAUSES* 4 * FMAPS];
__device__ float g_vbuf[NVARS * 2 * FMAPS];
__device__ float g_vh1 [NVARS * 2 * FMAPS];
__device__ float g_vh2 [NVARS * 2 * FMAPS];
__device__ float g_logits[NVARS];
__device__ float g_loss[1];
__device__ int   g_litidx[NEDGES];
__device__ int   g_varidx[NEDGES];
__device__ float g_sign [NEDGES];

// packed split weights (all 13 matrices)
__device__ __half2 g_Bcat[3342336];

// ================= fp16 split-precision tensor-core GEMM =================
// Logical: C[M,N] = A32[M,K] @ B[K,N] = Ahi@Bhi + (Ahi/s)@(Blo*s) + (Alo*s)@(Bhi/s)
// A is fp32 in gmem; hi/lo fp16 split happens during the smem fill.
// KC = 3*K; section = k0/K. Bcat (prebuilt) rows follow [hi ; lo*s ; hi/s].
// flags: 1=add bias, 2=relu, 4=accumulate into existing C
#define BMh 128
#define BNh 128
#define BKh 32
#define SA  40                  // half units per A smem row
#define SB  136                 // half2 units per B smem row
#define A_BYTES (BMh * SA * 2)  // 10240
#define B_BYTES (16 * SB * 4)   // 8704
#define STG_BYTES (A_BYTES + B_BYTES)   // 18944

__device__ __forceinline__ void cp16(uint32_t saddr, const void* g, int src_bytes)
{
    asm volatile("cp.async.ca.shared.global [%0], [%1], 16, %2;\n"
                 :: "r"(saddr), "l"(g), "r"(src_bytes));
}

__device__ __forceinline__ void mma16(float* c, uint32_t a0, uint32_t a1,
                                      uint32_t a2, uint32_t a3,
                                      uint32_t b0, uint32_t b1)
{
    asm volatile(
        "mma.sync.aligned.m16n8k16.row.col.f32.f16.f16.f32 "
        "{%0,%1,%2,%3}, {%4,%5,%6,%7}, {%8,%9}, {%0,%1,%2,%3};\n"
        : "+f"(c[0]), "+f"(c[1]), "+f"(c[2]), "+f"(c[3])
        : "r"(a0), "r"(a1), "r"(a2), "r"(a3), "r"(b0), "r"(b1));
}

__global__ __launch_bounds__(256, 2)
void tgemm16(const float* __restrict__ A, const __half2* __restrict__ Bp,
             const float* __restrict__ bias, float* __restrict__ C,
             int M, int N, int K, int flags)
{
    extern __shared__ __align__(16) char smraw[];
    const int tid  = threadIdx.x;
    const int warp = tid >> 5, lane = tid & 31;
    const int gid  = lane >> 2, ti = lane & 3;
    const int wm = warp >> 2, wn = warp & 3;
    const int warpRow = wm * 64, warpCol = wn * 32;
    const int bm = blockIdx.y * BMh, bn = blockIdx.x * BNh;
    const int KC  = 3 * K;
    const int nit = KC / BKh;

    const int ar = tid >> 1;
    const int cb = (tid & 1) * 16;
    const int arow_ok = (bm + ar) < M;
    const float* Arow = A + (size_t)(arow_ok ? (bm + ar) : 0) * K;

    float c[4][4][4];
#pragma unroll
    for (int mi = 0; mi < 4; mi++)
#pragma unroll
        for (int ni = 0; ni < 4; ni++)
#pragma unroll
            for (int r = 0; r < 4; r++) c[mi][ni][r] = 0.f;

    float4 f[4];
#pragma unroll
    for (int q = 0; q < 4; q++)
        f[q] = arow_ok ? *(const float4*)(Arow + cb + 4 * q)
                       : make_float4(0.f, 0.f, 0.f, 0.f);

    // ---- prefetch B stage 0 ----
    {
        __half2* Bs = (__half2*)(smraw + A_BYTES);
#pragma unroll
        for (int j = 0; j < 2; j++) {
            int idx = tid + j * 256;
            int br = idx >> 5, bc = (idx & 31) * 4;
            cp16((uint32_t)__cvta_generic_to_shared(Bs + br * SB + bc),
                 Bp + (size_t)br * N + bn + bc, 16);
        }
        asm volatile("cp.async.commit_group;\n");
    }

    for (int it = 0; it < nit; it++) {
        // ---- store A regs (stage it) into smem with scaled hi/lo conversion ----
        {
            const int k0  = it * BKh;
            const int sec = (k0 >= 2 * K) ? 2 : ((k0 >= K) ? 1 : 0);
            __half* As = (__half*)(smraw + (it & 1) * STG_BYTES);
            __half hbuf[16];
#pragma unroll
            for (int q = 0; q < 4; q++) {
                float x[4] = {f[q].x, f[q].y, f[q].z, f[q].w};
#pragma unroll
                for (int e = 0; e < 4; e++) {
                    __half h = __float2half_rn(x[e]);
                    if (sec == 0)
                        hbuf[q * 4 + e] = h;
                    else if (sec == 1)
                        hbuf[q * 4 + e] = __float2half_rn(__half2float(h) * SSC_INV);
                    else
                        hbuf[q * 4 + e] = __float2half_rn((x[e] - __half2float(h)) * SSC);
                }
            }
            *(uint4*)(As + ar * SA + cb)     = *(const uint4*)(hbuf);
            *(uint4*)(As + ar * SA + cb + 8) = *(const uint4*)(hbuf + 8);
        }

        // ---- B cp.async for stage it+1 ----
        if (it + 1 < nit) {
            const int kp0 = ((it + 1) * BKh) >> 1;
            __half2* Bs = (__half2*)(smraw + ((it + 1) & 1) * STG_BYTES + A_BYTES);
#pragma unroll
            for (int j = 0; j < 2; j++) {
                int idx = tid + j * 256;
                int br = idx >> 5, bc = (idx & 31) * 4;
                cp16((uint32_t)__cvta_generic_to_shared(Bs + br * SB + bc),
                     Bp + (size_t)(kp0 + br) * N + bn + bc, 16);
            }
            asm volatile("cp.async.commit_group;\n");
            asm volatile("cp.async.wait_group 1;\n");
        } else {
            asm volatile("cp.async.wait_group 0;\n");
        }
        __syncthreads();

        // ---- preload A regs for stage it+1 (overlaps MMA) ----
        if (it + 1 < nit) {
            const int k1  = (it + 1) * BKh;
            const int sec = k1 / K;
            const int scl = k1 - sec * K;
#pragma unroll
            for (int q = 0; q < 4; q++)
                f[q] = arow_ok ? *(const float4*)(Arow + scl + cb + 4 * q)
                               : make_float4(0.f, 0.f, 0.f, 0.f);
        }

        const __half* As   = (const __half*)(smraw + (it & 1) * STG_BYTES);
        const uint32_t* Au = (const uint32_t*)As;
        const uint32_t* Bu = (const uint32_t*)((const char*)As + A_BYTES);

#pragma unroll
        for (int kk = 0; kk < 2; kk++) {
            uint32_t a[4][4], b[4][2];
#pragma unroll
            for (int mi = 0; mi < 4; mi++) {
                int r0 = warpRow + mi * 16 + gid;
                a[mi][0] = Au[(r0)     * (SA / 2) + kk * 8 + ti];
                a[mi][1] = Au[(r0 + 8) * (SA / 2) + kk * 8 + ti];
                a[mi][2] = Au[(r0)     * (SA / 2) + kk * 8 + ti + 4];
                a[mi][3] = Au[(r0 + 8) * (SA / 2) + kk * 8 + ti + 4];
            }
#pragma unroll
            for (int ni = 0; ni < 4; ni++) {
                int cc = warpCol + ni * 8 + gid;
                b[ni][0] = Bu[(kk * 8 + ti)     * SB + cc];
                b[ni][1] = Bu[(kk * 8 + ti + 4) * SB + cc];
            }
#pragma unroll
            for (int mi = 0; mi < 4; mi++)
#pragma unroll
                for (int ni = 0; ni < 4; ni++)
                    mma16(c[mi][ni], a[mi][0], a[mi][1], a[mi][2], a[mi][3],
                          b[ni][0], b[ni][1]);
        }
        __syncthreads();
    }

    // ---- epilogue ----
#pragma unroll
    for (int mi = 0; mi < 4; mi++) {
        int r0 = bm + warpRow + mi * 16 + gid;
        int r1 = r0 + 8;
#pragma unroll
        for (int ni = 0; ni < 4; ni++) {
            int c0 = bn + warpCol + ni * 8 + ti * 2;
#pragma unroll
            for (int half_ = 0; half_ < 2; half_++) {
                int row = half_ ? r1 : r0;
                if (row >= M) continue;
                float v0 = c[mi][ni][half_ * 2 + 0];
                float v1 = c[mi][ni][half_ * 2 + 1];
                if (flags & 1) { v0 += bias[c0]; v1 += bias[c0 + 1]; }
                size_t o = (size_t)row * N + c0;
                if (flags & 4) { v0 += C[o]; v1 += C[o + 1]; }
                if (flags & 2) { v0 = fmaxf(v0, 0.f); v1 = fmaxf(v1, 0.f); }
                C[o] = v0; C[o + 1] = v1;
            }
        }
    }
}

// ---------------- weight split kernel ----------------
// B_cat packed half2: rows = 3K/2 half2-pairs; sections [hi ; lo*s ; hi/s]
__global__ void k_splitB(const float* __restrict__ B, __half2* __restrict__ out,
                         int K, int N)
{
    int idx = blockIdx.x * blockDim.x + threadIdx.x;
    int total = (3 * K / 2) * N;
    if (idx >= total) return;
    int kp = idx / N, n = idx % N;
    int kc0 = 2 * kp;
    int sec = kc0 / K, kk = kc0 % K;
    float x0 = B[(size_t)kk * N + n];
    float x1 = B[(size_t)(kk + 1) * N + n];
    __half h0 = __float2half_rn(x0), h1 = __float2half_rn(x1);
    __half v0, v1;
    if (sec == 0) {
        v0 = h0; v1 = h1;
    } else if (sec == 1) {
        v0 = __float2half_rn((x0 - __half2float(h0)) * SSC);
        v1 = __float2half_rn((x1 - __half2float(h1)) * SSC);
    } else {
        v0 = __float2half_rn(__half2float(h0) * SSC_INV);
        v1 = __float2half_rn(__half2float(h1) * SSC_INV);
    }
    out[idx] = __halves2half2(v0, v1);
}

// ---------------- elementwise / graph kernels ----------------
__global__ void k_build_edges(const int* __restrict__ lits,
                              int* litidx, int* varidx, float* sign)
{
    int e = blockIdx.x * blockDim.x + threadIdx.x;
    if (e >= NEDGES) return;
    int l = lits[e];
    int v = (l > 0 ? l : -l) - 1;
    varidx[e] = v;
    litidx[e] = (l > 0) ? v : (NVARS + v);
    sign[e]   = (l > 0) ? 1.f : -1.f;
}

__global__ void k_bcast_init(float* h, float* c, const float* __restrict__ init, int rows)
{
    int i = blockIdx.x * blockDim.x + threadIdx.x;
    if (i >= rows * FMAPS) return;
    h[i] = init[i & (FMAPS - 1)] * 0.0625f;   // 1/sqrt(256)
    c[i] = 0.f;
}

__global__ void k_zero(float* p, int n)
{
    int i = blockIdx.x * blockDim.x + threadIdx.x;
    if (i < n) p[i] = 0.f;
}

__global__ void k_gather_clause(const float* __restrict__ pre,
                                const int* __restrict__ litidx,
                                float* __restrict__ msgs)
{
    int idx = blockIdx.x * blockDim.x + threadIdx.x;
    if (idx >= NCLAUSES * FMAPS) return;
    int c = idx >> 8, f = idx & 255;
    int e = c * 3;
    float s = pre[(size_t)litidx[e]     * FMAPS + f]
            + pre[(size_t)litidx[e + 1] * FMAPS + f]
            + pre[(size_t)litidx[e + 2] * FMAPS + f];
    msgs[idx] = s;
}

__global__ void k_scatter_lit(const float* __restrict__ pre,
                              const int* __restrict__ litidx,
                              float* __restrict__ msgs)
{
    int idx = blockIdx.x * blockDim.x + threadIdx.x;
    if (idx >= NEDGES * FMAPS) return;
    int e = idx >> 8, f = idx & 255;
    int c = e / 3;
    atomicAdd(&msgs[(size_t)litidx[e] * FMAPS + f], pre[(size_t)c * FMAPS + f]);
}

__device__ __forceinline__ float sigf(float x) { return 1.f / (1.f + expf(-x)); }

__global__ void k_lstm_update(const float* __restrict__ z,
                              float* __restrict__ h, float* __restrict__ c, int rows)
{
    int idx = blockIdx.x * blockDim.x + threadIdx.x;
    if (idx >= rows * FMAPS) return;
    int r = idx >> 8, f = idx & 255;
    const float* zr = z + (size_t)r * (4 * FMAPS);
    float gi = zr[f], gf = zr[FMAPS + f], gg = zr[2 * FMAPS + f], go = zr[3 * FMAPS + f];
    float cn = sigf(gf) * c[idx] + sigf(gi) * tanhf(gg);
    c[idx] = cn;
    h[idx] = sigf(go) * tanhf(cn);
}

__global__ void k_flip(const float* __restrict__ lh, float* __restrict__ flip)
{
    int idx = blockIdx.x * blockDim.x + threadIdx.x;
    if (idx >= NLITS * FMAPS) return;
    int r = idx >> 8, f = idx & 255;
    int src = (r < NVARS) ? (r + NVARS) : (r - NVARS);
    flip[idx] = lh[(size_t)src * FMAPS + f];
}

__global__ void k_vbuf(const float* __restrict__ lh, float* __restrict__ vbuf)
{
    int idx = blockIdx.x * blockDim.x + threadIdx.x;
    if (idx >= NVARS * 2 * FMAPS) return;
    int v = idx >> 9, f = idx & 511;
    float val = (f < FMAPS) ? lh[(size_t)v * FMAPS + f]
                            : lh[(size_t)(NVARS + v) * FMAPS + (f - FMAPS)];
    vbuf[idx] = val;
}

__global__ void k_vote_out(const float* __restrict__ H, const float* __restrict__ W2,
                           const float* __restrict__ b2, float* __restrict__ logits)
{
    int warp = (blockIdx.x * blockDim.x + threadIdx.x) >> 5;
    int lane = threadIdx.x & 31;
    if (warp >= NVARS) return;
    const float* h = H + (size_t)warp * (2 * FMAPS);
    float s = 0.f;
#pragma unroll
    for (int k = lane; k < 2 * FMAPS; k += 32) s += h[k] * W2[k];
#pragma unroll
    for (int o = 16; o; o >>= 1) s += __shfl_down_sync(0xffffffffu, s, o);
    if (lane == 0) logits[warp] = s + b2[0];
}

__device__ __forceinline__ float softplusf(float x)
{
    return fmaxf(x, 0.f) + log1pf(expf(-fabsf(x)));
}

__global__ void k_loss(const float* __restrict__ logits,
                       const int* __restrict__ varidx,
                       const float* __restrict__ sign,
                       float* __restrict__ loss)
{
    __shared__ float red[256];
    int c = blockIdx.x * blockDim.x + threadIdx.x;
    float t = 0.f;
    if (c < NCLAUSES) {
        float s = 0.f;
#pragma unroll
        for (int k = 0; k < 3; k++) {
            int e = c * 3 + k;
            s += softplusf(logits[varidx[e]] * sign[e]);
        }
        float cv = expf(-s);
        float v = -logf(1.f - cv + 1e-8f);
        t = v * v;
    }
    red[threadIdx.x] = t;
    __syncthreads();
    for (int o = 128; o; o >>= 1) {
        if (threadIdx.x < o) red[threadIdx.x] += red[threadIdx.x + o];
        __syncthreads();
    }
    if (threadIdx.x == 0) atomicAdd(loss, red[0]);
}

__global__ void k_writeout(const float* __restrict__ logits,
                           const float* __restrict__ loss,
                           float* __restrict__ out, int out_size)
{
    int i = blockIdx.x * blockDim.x + threadIdx.x;
    if (i < NVARS && i < out_size) out[i] = logits[i];
    if (i == NVARS && out_size > NVARS) out[NVARS] = loss[0] / 32.0f;
}

// ---------------- host orchestration ----------------
static const int SMEM_BYTES16 = STG_BYTES * 2;   // 37888

static inline int gdiv(int a, int b) { return (a + b - 1) / b; }

static __half2* s_Bcat;

static inline void gemmsp(const float* A, size_t boff, const float* bias, float* C,
                          int M, int N, int K, int flags)
{
    dim3 g(N / BNh, gdiv(M, BMh));
    tgemm16<<<g, 256, SMEM_BYTES16>>>(A, s_Bcat + boff, bias, C, M, N, K, flags);
}

extern "C" void kernel_launch(void* const* d_in, const int* in_sizes, int n_in,
                              void* d_out, int out_size)
{
    static int smem_set = 0;
    if (!smem_set) {
        cudaFuncSetAttribute(tgemm16, cudaFuncAttributeMaxDynamicSharedMemorySize, SMEM_BYTES16);
        smem_set = 1;
    }

    int p = 1;
    if (n_in > 1 && in_sizes[1] == 1) p = 2;
    const int*   clause_lits = (const int*)d_in[0];
    const float* L_init = (const float*)d_in[p + 0];
    const float* C_init = (const float*)d_in[p + 1];
    const float* LC_W0  = (const float*)d_in[p + 2];
    const float* LC_b0  = (const float*)d_in[p + 3];
    const float* LC_W1  = (const float*)d_in[p + 4];
    const float* LC_b1  = (const float*)d_in[p + 5];
    const float* LC_W2  = (const float*)d_in[p + 6];
    const float* LC_b2  = (const float*)d_in[p + 7];
    const float* CL_W0  = (const float*)d_in[p + 8];
    const float* CL_b0  = (const float*)d_in[p + 9];
    const float* CL_W1  = (const float*)d_in[p + 10];
    const float* CL_b1  = (const float*)d_in[p + 11];
    const float* CL_W2  = (const float*)d_in[p + 12];
    const float* CL_b2  = (const float*)d_in[p + 13];
    const float* C_Wx   = (const float*)d_in[p + 14];
    const float* C_Wh   = (const float*)d_in[p + 15];
    const float* C_b    = (const float*)d_in[p + 16];
    const float* L_Wx   = (const float*)d_in[p + 17];
    const float* L_Wh   = (const float*)d_in[p + 18];
    const float* L_b    = (const float*)d_in[p + 19];
    const float* V_W0   = (const float*)d_in[p + 20];
    const float* V_b0   = (const float*)d_in[p + 21];
    const float* V_W1   = (const float*)d_in[p + 22];
    const float* V_b1   = (const float*)d_in[p + 23];
    const float* V_W2   = (const float*)d_in[p + 24];
    const float* V_b2   = (const float*)d_in[p + 25];
    float* out = (float*)d_out;

    float *lh, *lc, *ch, *cc, *h1, *h2, *cmsg, *lmsg, *flip, *z, *vbuf, *vh1, *vh2, *logits, *loss, *sign;
    int *litidx, *varidx;
    cudaGetSymbolAddress((void**)&lh,   g_lh);
    cudaGetSymbolAddress((void**)&lc,   g_lc);
    cudaGetSymbolAddress((void**)&ch,   g_ch);
    cudaGetSymbolAddress((void**)&cc,   g_cc);
    cudaGetSymbolAddress((void**)&h1,   g_h1);
    cudaGetSymbolAddress((void**)&h2,   g_h2);
    cudaGetSymbolAddress((void**)&cmsg, g_cmsg);
    cudaGetSymbolAddress((void**)&lmsg, g_lmsg);
    cudaGetSymbolAddress((void**)&flip, g_flip);
    cudaGetSymbolAddress((void**)&z,    g_z);
    cudaGetSymbolAddress((void**)&vbuf, g_vbuf);
    cudaGetSymbolAddress((void**)&vh1,  g_vh1);
    cudaGetSymbolAddress((void**)&vh2,  g_vh2);
    cudaGetSymbolAddress((void**)&logits, g_logits);
    cudaGetSymbolAddress((void**)&loss, g_loss);
    cudaGetSymbolAddress((void**)&sign, g_sign);
    cudaGetSymbolAddress((void**)&litidx, g_litidx);
    cudaGetSymbolAddress((void**)&varidx, g_varidx);
    cudaGetSymbolAddress((void**)&s_Bcat, g_Bcat);

    const float* L_Wx_top = L_Wx;                   // rows [0,256)   -> cl_msgs part
    const float* L_Wx_bot = L_Wx + 256 * 1024;      // rows [256,512) -> flipped part

    // ---- weight splits (B_cat), one region per matrix ----
    const size_t SZ_256_256  = (size_t)384 * 256;    // (3K/2)*N half2
    const size_t SZ_256_1024 = (size_t)384 * 1024;
    const size_t SZ_512_512  = (size_t)768 * 512;

    size_t off = 0;
    size_t o_LC0 = off; off += SZ_256_256;
    size_t o_LC1 = off; off += SZ_256_256;
    size_t o_LC2 = off; off += SZ_256_256;
    size_t o_CL0 = off; off += SZ_256_256;
    size_t o_CL1 = off; off += SZ_256_256;
    size_t o_CL2 = off; off += SZ_256_256;
    size_t o_CWx = off; off += SZ_256_1024;
    size_t o_CWh = off; off += SZ_256_1024;
    size_t o_LWxT= off; off += SZ_256_1024;
    size_t o_LWxB= off; off += SZ_256_1024;
    size_t o_LWh = off; off += SZ_256_1024;
    size_t o_VW0 = off; off += SZ_512_512;
    size_t o_VW1 = off; off += SZ_512_512;

    {
        int t1 = (int)SZ_256_256, t2 = (int)SZ_256_1024, t3 = (int)SZ_512_512;
        k_splitB<<<gdiv(t1, 256), 256>>>(LC_W0, s_Bcat + o_LC0, 256, 256);
        k_splitB<<<gdiv(t1, 256), 256>>>(LC_W1, s_Bcat + o_LC1, 256, 256);
        k_splitB<<<gdiv(t1, 256), 256>>>(LC_W2, s_Bcat + o_LC2, 256, 256);
        k_splitB<<<gdiv(t1, 256), 256>>>(CL_W0, s_Bcat + o_CL0, 256, 256);
        k_splitB<<<gdiv(t1, 256), 256>>>(CL_W1, s_Bcat + o_CL1, 256, 256);
        k_splitB<<<gdiv(t1, 256), 256>>>(CL_W2, s_Bcat + o_CL2, 256, 256);
        k_splitB<<<gdiv(t2, 256), 256>>>(C_Wx,     s_Bcat + o_CWx,  256, 1024);
        k_splitB<<<gdiv(t2, 256), 256>>>(C_Wh,     s_Bcat + o_CWh,  256, 1024);
        k_splitB<<<gdiv(t2, 256), 256>>>(L_Wx_top, s_Bcat + o_LWxT, 256, 1024);
        k_splitB<<<gdiv(t2, 256), 256>>>(L_Wx_bot, s_Bcat + o_LWxB, 256, 1024);
        k_splitB<<<gdiv(t2, 256), 256>>>(L_Wh,     s_Bcat + o_LWh,  256, 1024);
        k_splitB<<<gdiv(t3, 256), 256>>>(V_W0,     s_Bcat + o_VW0,  512, 512);
        k_splitB<<<gdiv(t3, 256), 256>>>(V_W1,     s_Bcat + o_VW1,  512, 512);
    }

    // ---- setup ----
    k_build_edges<<<gdiv(NEDGES, 256), 256>>>(clause_lits, litidx, varidx, sign);
    k_bcast_init<<<gdiv(NLITS * FMAPS, 256), 256>>>(lh, lc, L_init, NLITS);
    k_bcast_init<<<gdiv(NCLAUSES * FMAPS, 256), 256>>>(ch, cc, C_init, NCLAUSES);
    k_zero<<<1, 32>>>(loss, 1);

    // ---- 32 message-passing rounds ----
    for (int r = 0; r < 32; r++) {
        gemmsp(lh, o_LC0, LC_b0, h1, NLITS, FMAPS, FMAPS, 1 | 2);
        gemmsp(h1, o_LC1, LC_b1, h2, NLITS, FMAPS, FMAPS, 1 | 2);
        gemmsp(h2, o_LC2, LC_b2, h1, NLITS, FMAPS, FMAPS, 1);
        k_gather_clause<<<gdiv(NCLAUSES * FMAPS, 256), 256>>>(h1, litidx, cmsg);
        gemmsp(cmsg, o_CWx, C_b, z, NCLAUSES, 4 * FMAPS, FMAPS, 1);
        gemmsp(ch,   o_CWh, 0,   z, NCLAUSES, 4 * FMAPS, FMAPS, 4);
        k_lstm_update<<<gdiv(NCLAUSES * FMAPS, 256), 256>>>(z, ch, cc, NCLAUSES);
        gemmsp(ch, o_CL0, CL_b0, h1, NCLAUSES, FMAPS, FMAPS, 1 | 2);
        gemmsp(h1, o_CL1, CL_b1, h2, NCLAUSES, FMAPS, FMAPS, 1 | 2);
        gemmsp(h2, o_CL2, CL_b2, h1, NCLAUSES, FMAPS, FMAPS, 1);
        k_zero<<<gdiv(NLITS * FMAPS, 256), 256>>>(lmsg, NLITS * FMAPS);
        k_scatter_lit<<<gdiv(NEDGES * FMAPS, 256), 256>>>(h1, litidx, lmsg);
        k_flip<<<gdiv(NLITS * FMAPS, 256), 256>>>(lh, flip);
        gemmsp(lmsg, o_LWxT, L_b, z, NLITS, 4 * FMAPS, FMAPS, 1);
        gemmsp(flip, o_LWxB, 0,   z, NLITS, 4 * FMAPS, FMAPS, 4);
        gemmsp(lh,   o_LWh,  0,   z, NLITS, 4 * FMAPS, FMAPS, 4);
        k_lstm_update<<<gdiv(NLITS * FMAPS, 256), 256>>>(z, lh, lc, NLITS);
        k_vbuf<<<gdiv(NVARS * 2 * FMAPS, 256), 256>>>(lh, vbuf);
        gemmsp(vbuf, o_VW0, V_b0, vh1, NVARS, 2 * FMAPS, 2 * FMAPS, 1 | 2);
        gemmsp(vh1,  o_VW1, V_b1, vh2, NVARS, 2 * FMAPS, 2 * FMAPS, 1 | 2);
        k_vote_out<<<gdiv(NVARS * 32, 256), 256>>>(vh2, V_W2, V_b2, logits);
        k_loss<<<gdiv(NCLAUSES, 256), 256>>>(logits, varidx, sign, loss);
    }

    k_writeout<<<gdiv(NVARS + 1, 256), 256>>>(logits, loss, out, out_size);
}

// round 17
// speedup vs baseline: 1.5977x; 1.1260x over previous
#include <cuda_runtime.h>
#include <cuda_fp16.h>
#include <stdint.h>
#include <math.h>

#define NVARS    4000
#define NLITS    8000
#define NCLAUSES 16800
#define NEDGES   50400
#define FMAPS    256
#define DCAP     48

#define SSC     128.0f
#define SSC_INV 0.0078125f

// ---------------- device scratch (allocation-free) ----------------
__device__ float g_lh  [NLITS   * FMAPS];
__device__ float g_lc  [NLITS   * FMAPS];
__device__ float g_ch  [NCLAUSES* FMAPS];
__device__ float g_cc  [NCLAUSES* FMAPS];
__device__ float g_h1  [NCLAUSES* FMAPS];
__device__ float g_h2  [NCLAUSES* FMAPS];
__device__ float g_cmsg[NCLAUSES* FMAPS];
__device__ float g_lmsg[NLITS   * FMAPS];
__device__ float g_z   [NCLAUSES* 4 * FMAPS];
__device__ float g_vh1 [NVARS * 2 * FMAPS];
__device__ float g_vh2 [NVARS * 2 * FMAPS];
__device__ float g_logits[NVARS];
__device__ float g_loss[1];
__device__ int   g_litidx[NEDGES];
__device__ int   g_varidx[NEDGES];
__device__ float g_sign [NEDGES];
__device__ int   g_cur [NLITS];
__device__ int   g_adj [NLITS * DCAP];

// packed split weights (all matrices)
__device__ __half2 g_Bcat[3342336];

// ================= fp16 split-precision multi-source GEMM =================
// C[M,N] = sum_src A_src[M,256] @ W_src[256,N], each product done as
// Ahi@Bhi + (Ahi/s)@(Blo*s) + (Alo*s)@(Bhi/s).   KC = nsrc*768.
// A sources are fp32; hi/lo conversion happens during smem staging.
// Source 1 may carry a row offset (mod M) to implement the literal flip.
// flags: 1=add bias, 2=relu, 4=accumulate into existing C
#define BMh 128
#define BNh 128
#define BKh 32
#define SA  40                  // half units per A smem row
#define SB  136                 // half2 units per B smem row
#define A_BYTES (BMh * SA * 2)  // 10240
#define B_BYTES (16 * SB * 4)   // 8704
#define STG_BYTES (A_BYTES + B_BYTES)

__device__ __forceinline__ void cp16(uint32_t saddr, const void* g, int src_bytes)
{
    asm volatile("cp.async.ca.shared.global [%0], [%1], 16, %2;\n"
                 :: "r"(saddr), "l"(g), "r"(src_bytes));
}

__device__ __forceinline__ void mma16(float* c, uint32_t a0, uint32_t a1,
                                      uint32_t a2, uint32_t a3,
                                      uint32_t b0, uint32_t b1)
{
    asm volatile(
        "mma.sync.aligned.m16n8k16.row.col.f32.f16.f16.f32 "
        "{%0,%1,%2,%3}, {%4,%5,%6,%7}, {%8,%9}, {%0,%1,%2,%3};\n"
        : "+f"(c[0]), "+f"(c[1]), "+f"(c[2]), "+f"(c[3])
        : "r"(a0), "r"(a1), "r"(a2), "r"(a3), "r"(b0), "r"(b1));
}

__device__ __forceinline__ void aload(float4 f[4], int k0,
    const float* A0, const float* A1, const float* A2,
    int st0, int st1, int st2, int ro1,
    int bm, int ar, int cb, int M, int ok)
{
    int src  = k0 / 768;
    int kin  = k0 - src * 768;
    int scol = kin & 255;
    const float* base = (src == 0) ? A0 : ((src == 1) ? A1 : A2);
    int st = (src == 0) ? st0 : ((src == 1) ? st1 : st2);
    int r  = bm + ar;
    if (src == 1) { r += ro1; if (r >= M) r -= M; }
    const float* p = base + (size_t)(ok ? r : 0) * st + scol + cb;
#pragma unroll
    for (int q = 0; q < 4; q++)
        f[q] = ok ? *(const float4*)(p + 4 * q) : make_float4(0.f, 0.f, 0.f, 0.f);
}

__global__ __launch_bounds__(256, 2)
void tgemm16(const float* __restrict__ A0, const float* __restrict__ A1,
             const float* __restrict__ A2,
             int st0, int st1, int st2, int ro1, int nsrc,
             const __half2* __restrict__ Bp,
             const float* __restrict__ bias, float* __restrict__ C,
             int M, int N, int flags)
{
    extern __shared__ __align__(16) char smraw[];
    const int tid  = threadIdx.x;
    const int warp = tid >> 5, lane = tid & 31;
    const int gid  = lane >> 2, ti = lane & 3;
    const int wm = warp >> 2, wn = warp & 3;
    const int warpRow = wm * 64, warpCol = wn * 32;
    const int bm = blockIdx.y * BMh, bn = blockIdx.x * BNh;
    const int nit = nsrc * 24;          // nsrc*768/32

    const int ar = tid >> 1;
    const int cb = (tid & 1) * 16;
    const int arow_ok = (bm + ar) < M;

    float c[4][4][4];
#pragma unroll
    for (int mi = 0; mi < 4; mi++)
#pragma unroll
        for (int ni = 0; ni < 4; ni++)
#pragma unroll
            for (int r = 0; r < 4; r++) c[mi][ni][r] = 0.f;

    float4 f[4];
    aload(f, 0, A0, A1, A2, st0, st1, st2, ro1, bm, ar, cb, M, arow_ok);

    // ---- prefetch B stage 0 ----
    {
        __half2* Bs = (__half2*)(smraw + A_BYTES);
#pragma unroll
        for (int j = 0; j < 2; j++) {
            int idx = tid + j * 256;
            int br = idx >> 5, bc = (idx & 31) * 4;
            cp16((uint32_t)__cvta_generic_to_shared(Bs + br * SB + bc),
                 Bp + (size_t)br * N + bn + bc, 16);
        }
        asm volatile("cp.async.commit_group;\n");
    }

    for (int it = 0; it < nit; it++) {
        // ---- store A regs (stage it) into smem with scaled hi/lo conversion ----
        {
            const int k0  = it * BKh;
            const int sec = (k0 - (k0 / 768) * 768) >> 8;
            __half* As = (__half*)(smraw + (it & 1) * STG_BYTES);
            __half hbuf[16];
#pragma unroll
            for (int q = 0; q < 4; q++) {
                float x[4] = {f[q].x, f[q].y, f[q].z, f[q].w};
#pragma unroll
                for (int e = 0; e < 4; e++) {
                    __half h = __float2half_rn(x[e]);
                    if (sec == 0)
                        hbuf[q * 4 + e] = h;
                    else if (sec == 1)
                        hbuf[q * 4 + e] = __float2half_rn(__half2float(h) * SSC_INV);
                    else
                        hbuf[q * 4 + e] = __float2half_rn((x[e] - __half2float(h)) * SSC);
                }
            }
            *(uint4*)(As + ar * SA + cb)     = *(const uint4*)(hbuf);
            *(uint4*)(As + ar * SA + cb + 8) = *(const uint4*)(hbuf + 8);
        }

        // ---- B cp.async for stage it+1 ----
        if (it + 1 < nit) {
            const int kp0 = ((it + 1) * BKh) >> 1;
            __half2* Bs = (__half2*)(smraw + ((it + 1) & 1) * STG_BYTES + A_BYTES);
#pragma unroll
            for (int j = 0; j < 2; j++) {
                int idx = tid + j * 256;
                int br = idx >> 5, bc = (idx & 31) * 4;
                cp16((uint32_t)__cvta_generic_to_shared(Bs + br * SB + bc),
                     Bp + (size_t)(kp0 + br) * N + bn + bc, 16);
            }
            asm volatile("cp.async.commit_group;\n");
            asm volatile("cp.async.wait_group 1;\n");
        } else {
            asm volatile("cp.async.wait_group 0;\n");
        }
        __syncthreads();

        // ---- preload A regs for stage it+1 (overlaps MMA) ----
        if (it + 1 < nit)
            aload(f, (it + 1) * BKh, A0, A1, A2, st0, st1, st2, ro1,
                  bm, ar, cb, M, arow_ok);

        const __half* As   = (const __half*)(smraw + (it & 1) * STG_BYTES);
        const uint32_t* Au = (const uint32_t*)As;
        const uint32_t* Bu = (const uint32_t*)((const char*)As + A_BYTES);

#pragma unroll
        for (int kk = 0; kk < 2; kk++) {
            uint32_t a[4][4], b[4][2];
#pragma unroll
            for (int mi = 0; mi < 4; mi++) {
                int r0 = warpRow + mi * 16 + gid;
                a[mi][0] = Au[(r0)     * (SA / 2) + kk * 8 + ti];
                a[mi][1] = Au[(r0 + 8) * (SA / 2) + kk * 8 + ti];
                a[mi][2] = Au[(r0)     * (SA / 2) + kk * 8 + ti + 4];
                a[mi][3] = Au[(r0 + 8) * (SA / 2) + kk * 8 + ti + 4];
            }
#pragma unroll
            for (int ni = 0; ni < 4; ni++) {
                int cc = warpCol + ni * 8 + gid;
                b[ni][0] = Bu[(kk * 8 + ti)     * SB + cc];
                b[ni][1] = Bu[(kk * 8 + ti + 4) * SB + cc];
            }
#pragma unroll
            for (int mi = 0; mi < 4; mi++)
#pragma unroll
                for (int ni = 0; ni < 4; ni++)
                    mma16(c[mi][ni], a[mi][0], a[mi][1], a[mi][2], a[mi][3],
                          b[ni][0], b[ni][1]);
        }
        __syncthreads();
    }

    // ---- epilogue ----
#pragma unroll
    for (int mi = 0; mi < 4; mi++) {
        int r0 = bm + warpRow + mi * 16 + gid;
        int r1 = r0 + 8;
#pragma unroll
        for (int ni = 0; ni < 4; ni++) {
            int c0 = bn + warpCol + ni * 8 + ti * 2;
#pragma unroll
            for (int half_ = 0; half_ < 2; half_++) {
                int row = half_ ? r1 : r0;
                if (row >= M) continue;
                float v0 = c[mi][ni][half_ * 2 + 0];
                float v1 = c[mi][ni][half_ * 2 + 1];
                if (flags & 1) { v0 += bias[c0]; v1 += bias[c0 + 1]; }
                size_t o = (size_t)row * N + c0;
                if (flags & 4) { v0 += C[o]; v1 += C[o + 1]; }
                if (flags & 2) { v0 = fmaxf(v0, 0.f); v1 = fmaxf(v1, 0.f); }
                C[o] = v0; C[o + 1] = v1;
            }
        }
    }
}

// ---------------- weight split kernel ----------------
// B_cat packed half2: rows = 3K/2 half2-pairs; sections [hi ; lo*s ; hi/s]
__global__ void k_splitB(const float* __restrict__ B, __half2* __restrict__ out,
                         int K, int N)
{
    int idx = blockIdx.x * blockDim.x + threadIdx.x;
    int total = (3 * K / 2) * N;
    if (idx >= total) return;
    int kp = idx / N, n = idx % N;
    int kc0 = 2 * kp;
    int sec = kc0 / K, kk = kc0 % K;
    float x0 = B[(size_t)kk * N + n];
    float x1 = B[(size_t)(kk + 1) * N + n];
    __half h0 = __float2half_rn(x0), h1 = __float2half_rn(x1);
    __half v0, v1;
    if (sec == 0) {
        v0 = h0; v1 = h1;
    } else if (sec == 1) {
        v0 = __float2half_rn((x0 - __half2float(h0)) * SSC);
        v1 = __float2half_rn((x1 - __half2float(h1)) * SSC);
    } else {
        v0 = __float2half_rn(__half2float(h0) * SSC_INV);
        v1 = __float2half_rn(__half2float(h1) * SSC_INV);
    }
    out[idx] = __halves2half2(v0, v1);
}

// ---------------- graph setup / CSR kernels ----------------
__global__ void k_build_edges(const int* __restrict__ lits,
                              int* litidx, int* varidx, float* sign)
{
    int e = blockIdx.x * blockDim.x + threadIdx.x;
    if (e >= NEDGES) return;
    int l = lits[e];
    int v = (l > 0 ? l : -l) - 1;
    varidx[e] = v;
    litidx[e] = (l > 0) ? v : (NVARS + v);
    sign[e]   = (l > 0) ? 1.f : -1.f;
}

__global__ void k_csr_zero(int* cur)
{
    int i = blockIdx.x * blockDim.x + threadIdx.x;
    if (i < NLITS) cur[i] = 0;
}

__global__ void k_csr_fill(const int* __restrict__ litidx, int* cur, int* adj)
{
    int e = blockIdx.x * blockDim.x + threadIdx.x;
    if (e >= NEDGES) return;
    int lit = litidx[e];
    int slot = atomicAdd(&cur[lit], 1);
    if (slot < DCAP) adj[lit * DCAP + slot] = e / 3;
}

__global__ void k_csr_sort(int* cur, int* adj)
{
    int lit = blockIdx.x * blockDim.x + threadIdx.x;
    if (lit >= NLITS) return;
    int n = cur[lit]; if (n > DCAP) n = DCAP;
    int* a = adj + lit * DCAP;
    for (int i = 1; i < n; i++) {
        int key = a[i], j = i - 1;
        while (j >= 0 && a[j] > key) { a[j + 1] = a[j]; j--; }
        a[j + 1] = key;
    }
}

__global__ void k_bcast_init(float* h, float* c, const float* __restrict__ init, int rows)
{
    int i = blockIdx.x * blockDim.x + threadIdx.x;
    if (i >= rows * FMAPS) return;
    h[i] = init[i & (FMAPS - 1)] * 0.0625f;   // 1/sqrt(256)
    c[i] = 0.f;
}

__global__ void k_zero(float* p, int n)
{
    int i = blockIdx.x * blockDim.x + threadIdx.x;
    if (i < n) p[i] = 0.f;
}

// lc_msgs[c] = sum over 3 literals of lc_pre[lit]   (deterministic)
__global__ void k_gather_clause(const float* __restrict__ pre,
                                const int* __restrict__ litidx,
                                float* __restrict__ msgs)
{
    int idx = blockIdx.x * blockDim.x + threadIdx.x;
    if (idx >= NCLAUSES * FMAPS) return;
    int c = idx >> 8, f = idx & 255;
    int e = c * 3;
    float s = pre[(size_t)litidx[e]     * FMAPS + f]
            + pre[(size_t)litidx[e + 1] * FMAPS + f]
            + pre[(size_t)litidx[e + 2] * FMAPS + f];
    msgs[idx] = s;
}

// cl_msgs[lit] = sum over sorted clause list (deterministic, no atomics)
__global__ void k_gather_lit(const float* __restrict__ pre,
                             const int* __restrict__ cur,
                             const int* __restrict__ adj,
                             float* __restrict__ msgs)
{
    int idx = blockIdx.x * blockDim.x + threadIdx.x;
    if (idx >= NLITS * FMAPS) return;
    int lit = idx >> 8, f = idx & 255;
    int n = cur[lit]; if (n > DCAP) n = DCAP;
    const int* a = adj + lit * DCAP;
    float s = 0.f;
    for (int j = 0; j < n; j++)
        s += pre[(size_t)a[j] * FMAPS + f];
    msgs[idx] = s;
}

__device__ __forceinline__ float sigf(float x) { return 1.f / (1.f + expf(-x)); }

__global__ void k_lstm_update(const float* __restrict__ z,
                              float* __restrict__ h, float* __restrict__ c, int rows)
{
    int idx = blockIdx.x * blockDim.x + threadIdx.x;
    if (idx >= rows * FMAPS) return;
    int r = idx >> 8, f = idx & 255;
    const float* zr = z + (size_t)r * (4 * FMAPS);
    float gi = zr[f], gf = zr[FMAPS + f], gg = zr[2 * FMAPS + f], go = zr[3 * FMAPS + f];
    float cn = sigf(gf) * c[idx] + sigf(gi) * tanhf(gg);
    c[idx] = cn;
    h[idx] = sigf(go) * tanhf(cn);
}

__global__ void k_vote_out(const float* __restrict__ H, const float* __restrict__ W2,
                           const float* __restrict__ b2, float* __restrict__ logits)
{
    int warp = (blockIdx.x * blockDim.x + threadIdx.x) >> 5;
    int lane = threadIdx.x & 31;
    if (warp >= NVARS) return;
    const float* h = H + (size_t)warp * (2 * FMAPS);
    float s = 0.f;
#pragma unroll
    for (int k = lane; k < 2 * FMAPS; k += 32) s += h[k] * W2[k];
#pragma unroll
    for (int o = 16; o; o >>= 1) s += __shfl_down_sync(0xffffffffu, s, o);
    if (lane == 0) logits[warp] = s + b2[0];
}

__device__ __forceinline__ float softplusf(float x)
{
    return fmaxf(x, 0.f) + log1pf(expf(-fabsf(x)));
}

__global__ void k_loss(const float* __restrict__ logits,
                       const int* __restrict__ varidx,
                       const float* __restrict__ sign,
                       float* __restrict__ loss)
{
    __shared__ float red[256];
    int c = blockIdx.x * blockDim.x + threadIdx.x;
    float t = 0.f;
    if (c < NCLAUSES) {
        float s = 0.f;
#pragma unroll
        for (int k = 0; k < 3; k++) {
            int e = c * 3 + k;
            s += softplusf(logits[varidx[e]] * sign[e]);
        }
        float cv = expf(-s);
        float v = -logf(1.f - cv + 1e-8f);
        t = v * v;
    }
    red[threadIdx.x] = t;
    __syncthreads();
    for (int o = 128; o; o >>= 1) {
        if (threadIdx.x < o) red[threadIdx.x] += red[threadIdx.x + o];
        __syncthreads();
    }
    if (threadIdx.x == 0) atomicAdd(loss, red[0]);
}

__global__ void k_writeout(const float* __restrict__ logits,
                           const float* __restrict__ loss,
                           float* __restrict__ out, int out_size)
{
    int i = blockIdx.x * blockDim.x + threadIdx.x;
    if (i < NVARS && i < out_size) out[i] = logits[i];
    if (i == NVARS && out_size > NVARS) out[NVARS] = loss[0] / 32.0f;
}

// ---------------- host orchestration ----------------
static const int SMEM_BYTES16 = STG_BYTES * 2;

static inline int gdiv(int a, int b) { return (a + b - 1) / b; }

static __half2* s_Bcat;

static inline void gemm1(const float* A, size_t boff, const float* bias, float* C,
                         int M, int N, int flags)
{
    dim3 g(N / BNh, gdiv(M, BMh));
    tgemm16<<<g, 256, SMEM_BYTES16>>>(A, A, A, 256, 256, 256, 0, 1,
                                      s_Bcat + boff, bias, C, M, N, flags);
}

static inline void gemm2(const float* A0, int st0, const float* A1, int st1,
                         size_t boff, const float* bias, float* C,
                         int M, int N, int flags)
{
    dim3 g(N / BNh, gdiv(M, BMh));
    tgemm16<<<g, 256, SMEM_BYTES16>>>(A0, A1, A1, st0, st1, st1, 0, 2,
                                      s_Bcat + boff, bias, C, M, N, flags);
}

static inline void gemm3f(const float* A0, const float* A1, const float* A2,
                          int ro1, size_t boff, const float* bias, float* C,
                          int M, int N, int flags)
{
    dim3 g(N / BNh, gdiv(M, BMh));
    tgemm16<<<g, 256, SMEM_BYTES16>>>(A0, A1, A2, 256, 256, 256, ro1, 3,
                                      s_Bcat + boff, bias, C, M, N, flags);
}

extern "C" void kernel_launch(void* const* d_in, const int* in_sizes, int n_in,
                              void* d_out, int out_size)
{
    static int smem_set = 0;
    if (!smem_set) {
        cudaFuncSetAttribute(tgemm16, cudaFuncAttributeMaxDynamicSharedMemorySize, SMEM_BYTES16);
        smem_set = 1;
    }

    int p = 1;
    if (n_in > 1 && in_sizes[1] == 1) p = 2;
    const int*   clause_lits = (const int*)d_in[0];
    const float* L_init = (const float*)d_in[p + 0];
    const float* C_init = (const float*)d_in[p + 1];
    const float* LC_W0  = (const float*)d_in[p + 2];
    const float* LC_b0  = (const float*)d_in[p + 3];
    const float* LC_W1  = (const float*)d_in[p + 4];
    const float* LC_b1  = (const float*)d_in[p + 5];
    const float* LC_W2  = (const float*)d_in[p + 6];
    const float* LC_b2  = (const float*)d_in[p + 7];
    const float* CL_W0  = (const float*)d_in[p + 8];
    const float* CL_b0  = (const float*)d_in[p + 9];
    const float* CL_W1  = (const float*)d_in[p + 10];
    const float* CL_b1  = (const float*)d_in[p + 11];
    const float* CL_W2  = (const float*)d_in[p + 12];
    const float* CL_b2  = (const float*)d_in[p + 13];
    const float* C_Wx   = (const float*)d_in[p + 14];
    const float* C_Wh   = (const float*)d_in[p + 15];
    const float* C_b    = (const float*)d_in[p + 16];
    const float* L_Wx   = (const float*)d_in[p + 17];
    const float* L_Wh   = (const float*)d_in[p + 18];
    const float* L_b    = (const float*)d_in[p + 19];
    const float* V_W0   = (const float*)d_in[p + 20];
    const float* V_b0   = (const float*)d_in[p + 21];
    const float* V_W1   = (const float*)d_in[p + 22];
    const float* V_b1   = (const float*)d_in[p + 23];
    const float* V_W2   = (const float*)d_in[p + 24];
    const float* V_b2   = (const float*)d_in[p + 25];
    float* out = (float*)d_out;

    float *lh, *lc, *ch, *cc, *h1, *h2, *cmsg, *lmsg, *z, *vh1, *vh2, *logits, *loss, *sign;
    int *litidx, *varidx, *cur, *adj;
    cudaGetSymbolAddress((void**)&lh,   g_lh);
    cudaGetSymbolAddress((void**)&lc,   g_lc);
    cudaGetSymbolAddress((void**)&ch,   g_ch);
    cudaGetSymbolAddress((void**)&cc,   g_cc);
    cudaGetSymbolAddress((void**)&h1,   g_h1);
    cudaGetSymbolAddress((void**)&h2,   g_h2);
    cudaGetSymbolAddress((void**)&cmsg, g_cmsg);
    cudaGetSymbolAddress((void**)&lmsg, g_lmsg);
    cudaGetSymbolAddress((void**)&z,    g_z);
    cudaGetSymbolAddress((void**)&vh1,  g_vh1);
    cudaGetSymbolAddress((void**)&vh2,  g_vh2);
    cudaGetSymbolAddress((void**)&logits, g_logits);
    cudaGetSymbolAddress((void**)&loss, g_loss);
    cudaGetSymbolAddress((void**)&sign, g_sign);
    cudaGetSymbolAddress((void**)&litidx, g_litidx);
    cudaGetSymbolAddress((void**)&varidx, g_varidx);
    cudaGetSymbolAddress((void**)&cur, g_cur);
    cudaGetSymbolAddress((void**)&adj, g_adj);
    cudaGetSymbolAddress((void**)&s_Bcat, g_Bcat);

    const float* L_Wx_top = L_Wx;                   // rows [0,256)   -> cl_msgs
    const float* L_Wx_bot = L_Wx + 256 * 1024;      // rows [256,512) -> flipped

    // ---- weight splits (B_cat) ----
    const size_t SZ_256_256  = (size_t)384 * 256;
    const size_t SZ_256_1024 = (size_t)384 * 1024;
    const size_t SZ_256_512  = (size_t)384 * 512;

    size_t off = 0;
    size_t o_LC0 = off; off += SZ_256_256;
    size_t o_LC1 = off; off += SZ_256_256;
    size_t o_LC2 = off; off += SZ_256_256;
    size_t o_CL0 = off; off += SZ_256_256;
    size_t o_CL1 = off; off += SZ_256_256;
    size_t o_CL2 = off; off += SZ_256_256;
    size_t o_CW  = off; off += 2 * SZ_256_1024;     // [CWx ; CWh]
    size_t o_LW  = off; off += 3 * SZ_256_1024;     // [LWx_top ; LWx_bot ; LWh]
    size_t o_VW0 = off; off += 2 * SZ_256_512;      // [VW0 top ; VW0 bot]
    size_t o_VW1 = off; off += 2 * SZ_256_512;      // [VW1 top ; VW1 bot]

    {
        int t1 = (int)SZ_256_256, t2 = (int)SZ_256_1024, t3 = (int)SZ_256_512;
        k_splitB<<<gdiv(t1, 256), 256>>>(LC_W0, s_Bcat + o_LC0, 256, 256);
        k_splitB<<<gdiv(t1, 256), 256>>>(LC_W1, s_Bcat + o_LC1, 256, 256);
        k_splitB<<<gdiv(t1, 256), 256>>>(LC_W2, s_Bcat + o_LC2, 256, 256);
        k_splitB<<<gdiv(t1, 256), 256>>>(CL_W0, s_Bcat + o_CL0, 256, 256);
        k_splitB<<<gdiv(t1, 256), 256>>>(CL_W1, s_Bcat + o_CL1, 256, 256);
        k_splitB<<<gdiv(t1, 256), 256>>>(CL_W2, s_Bcat + o_CL2, 256, 256);
        k_splitB<<<gdiv(t2, 256), 256>>>(C_Wx,     s_Bcat + o_CW,                  256, 1024);
        k_splitB<<<gdiv(t2, 256), 256>>>(C_Wh,     s_Bcat + o_CW + SZ_256_1024,    256, 1024);
        k_splitB<<<gdiv(t2, 256), 256>>>(L_Wx_top, s_Bcat + o_LW,                  256, 1024);
        k_splitB<<<gdiv(t2, 256), 256>>>(L_Wx_bot, s_Bcat + o_LW + SZ_256_1024,    256, 1024);
        k_splitB<<<gdiv(t2, 256), 256>>>(L_Wh,     s_Bcat + o_LW + 2*SZ_256_1024,  256, 1024);
        k_splitB<<<gdiv(t3, 256), 256>>>(V_W0,             s_Bcat + o_VW0,              256, 512);
        k_splitB<<<gdiv(t3, 256), 256>>>(V_W0 + 256 * 512, s_Bcat + o_VW0 + SZ_256_512, 256, 512);
        k_splitB<<<gdiv(t3, 256), 256>>>(V_W1,             s_Bcat + o_VW1,              256, 512);
        k_splitB<<<gdiv(t3, 256), 256>>>(V_W1 + 256 * 512, s_Bcat + o_VW1 + SZ_256_512, 256, 512);
    }

    // ---- setup: edges + deterministic CSR (sorted per-literal clause lists) ----
    k_build_edges<<<gdiv(NEDGES, 256), 256>>>(clause_lits, litidx, varidx, sign);
    k_csr_zero<<<gdiv(NLITS, 256), 256>>>(cur);
    k_csr_fill<<<gdiv(NEDGES, 256), 256>>>(litidx, cur, adj);
    k_csr_sort<<<gdiv(NLITS, 256), 256>>>(cur, adj);
    k_bcast_init<<<gdiv(NLITS * FMAPS, 256), 256>>>(lh, lc, L_init, NLITS);
    k_bcast_init<<<gdiv(NCLAUSES * FMAPS, 256), 256>>>(ch, cc, C_init, NCLAUSES);
    k_zero<<<1, 32>>>(loss, 1);

    // ---- 32 message-passing rounds ----
    for (int r = 0; r < 32; r++) {
        // literal MLP3 -> lc_pre (h1)
        gemm1(lh, o_LC0, LC_b0, h1, NLITS, FMAPS, 1 | 2);
        gemm1(h1, o_LC1, LC_b1, h2, NLITS, FMAPS, 1 | 2);
        gemm1(h2, o_LC2, LC_b2, h1, NLITS, FMAPS, 1);
        k_gather_clause<<<gdiv(NCLAUSES * FMAPS, 256), 256>>>(h1, litidx, cmsg);
        // clause LSTM: z = [cmsg|ch] @ [CWx;CWh] + b   (single fused GEMM)
        gemm2(cmsg, 256, ch, 256, o_CW, C_b, z, NCLAUSES, 4 * FMAPS, 1);
        k_lstm_update<<<gdiv(NCLAUSES * FMAPS, 256), 256>>>(z, ch, cc, NCLAUSES);
        // clause MLP3 -> cl_pre (h1)
        gemm1(ch, o_CL0, CL_b0, h1, NCLAUSES, FMAPS, 1 | 2);
        gemm1(h1, o_CL1, CL_b1, h2, NCLAUSES, FMAPS, 1 | 2);
        gemm1(h2, o_CL2, CL_b2, h1, NCLAUSES, FMAPS, 1);
        // deterministic gather clause->literal
        k_gather_lit<<<gdiv(NLITS * FMAPS, 256), 256>>>(h1, cur, adj, lmsg);
        // literal LSTM: z = [lmsg|flip(lh)|lh] @ [LWxT;LWxB;LWh] + b (fused, flip in-GEMM)
        gemm3f(lmsg, lh, lh, NVARS, o_LW, L_b, z, NLITS, 4 * FMAPS, 1);
        k_lstm_update<<<gdiv(NLITS * FMAPS, 256), 256>>>(z, lh, lc, NLITS);
        // vote (2-source concat, no vbuf)
        gemm2(lh, 256, lh + (size_t)NVARS * FMAPS, 256, o_VW0, V_b0, vh1, NVARS, 2 * FMAPS, 1 | 2);
        gemm2(vh1, 512, vh1 + 256, 512, o_VW1, V_b1, vh2, NVARS, 2 * FMAPS, 1 | 2);
        k_vote_out<<<gdiv(NVARS * 32, 256), 256>>>(vh2, V_W2, V_b2, logits);
        k_loss<<<gdiv(NCLAUSES, 256), 256>>>(logits, varidx, sign, loss);
    }

    k_writeout<<<gdiv(NVARS + 1, 256), 256>>>(logits, loss, out, out_size);
}